// round 10
// baseline (speedup 1.0000x reference)
#include <cuda_runtime.h>
#include <cuda_bf16.h>

#define BB   16
#define NN   2048
#define FIN  128
#define FO   64
#define TI   128
#define TJ   64
#define SPLITS 4
#define NT   (NN / SPLITS / TJ)   // 8
#define ALPHA 0.2f

// dynamic smem layout (bytes) for attn kernel
#define SM_PHI  0          // p hi  [128 x 128B]
#define SM_PLO  16384      // p lo
#define SM_WHHI 32768      // wh hi [2][64 x 128B]
#define SM_WHLO 49152      // wh lo [2][64 x 128B]
#define SM_FJ   65536      // fj    [2][64 floats]
#define SM_TOTAL 66048

// ---- scratch ----
__device__ float    g_Wh[BB * NN * FO];
__device__ float    g_fi[BB * NN];
__device__ float    g_fj[BB * NN];
__device__ unsigned g_WhT_hi[BB * FO * (NN / 2)];   // bf16x2 [b][o][j/2] (n-major)
__device__ unsigned g_WhT_lo[BB * FO * (NN / 2)];
__device__ float    g_part[SPLITS * BB * NN * FO];
__device__ float    g_rsum[SPLITS * 2 * BB * NN];   // 2 j-half partials per split

// ---- f32x2 helpers (wh kernel) ----
__device__ __forceinline__ void fma2(unsigned long long& d, unsigned long long a, unsigned long long b) {
    asm("fma.rn.f32x2 %0, %1, %2, %0;" : "+l"(d) : "l"(a), "l"(b));
}
__device__ __forceinline__ unsigned long long pack2(float x, float y) {
    unsigned long long r; asm("mov.b64 %0, {%1, %2};" : "=l"(r) : "f"(x), "f"(y)); return r;
}
__device__ __forceinline__ float2 unpack2(unsigned long long v) {
    float2 r; asm("mov.b64 {%0, %1}, %2;" : "=f"(r.x), "=f"(r.y) : "l"(v)); return r;
}

// ---- cp.async ----
__device__ __forceinline__ void cpasync16(unsigned s, const void* g) {
    asm volatile("cp.async.cg.shared.global [%0], [%1], 16;" :: "r"(s), "l"(g) : "memory");
}
__device__ __forceinline__ void cpasync_commit() { asm volatile("cp.async.commit_group;" ::: "memory"); }
__device__ __forceinline__ void cpasync_wait_all() {
    asm volatile("cp.async.wait_group 0;" ::: "memory");
}

// ---- tensor-core (base ISA) ----
__device__ __forceinline__ void ldm_x4(unsigned* d, unsigned saddr) {
    asm volatile("ldmatrix.sync.aligned.m8n8.x4.shared.b16 {%0,%1,%2,%3}, [%4];"
                 : "=r"(d[0]), "=r"(d[1]), "=r"(d[2]), "=r"(d[3]) : "r"(saddr));
}
__device__ __forceinline__ void mma_bf16(float* d, const unsigned* a, unsigned b0, unsigned b1) {
    asm volatile("mma.sync.aligned.m16n8k16.row.col.f32.bf16.bf16.f32 "
                 "{%0,%1,%2,%3}, {%4,%5,%6,%7}, {%8,%9}, {%0,%1,%2,%3};"
                 : "+f"(d[0]), "+f"(d[1]), "+f"(d[2]), "+f"(d[3])
                 : "r"(a[0]), "r"(a[1]), "r"(a[2]), "r"(a[3]), "r"(b0), "r"(b1));
}

__device__ __forceinline__ unsigned pack_bf16x2(float lo_v, float hi_v) {
    unsigned r; asm("cvt.rn.bf16x2.f32 %0, %1, %2;" : "=r"(r) : "f"(hi_v), "f"(lo_v)); return r;
}
__device__ __forceinline__ void split2(float v0, float v1, unsigned& hi, unsigned& lo) {
    unsigned b0 = __float_as_uint(v0), b1 = __float_as_uint(v1);
    hi = (b0 >> 16) | (b1 & 0xFFFF0000u);
    float h0 = __uint_as_float(b0 & 0xFFFF0000u);
    float h1 = __uint_as_float(b1 & 0xFFFF0000u);
    lo = pack_bf16x2(v0 - h0, v1 - h1);
}

// ============================================================
// Kernel 1: Wh = h @ W (+ masked f_i, f_j)
// ============================================================
__global__ __launch_bounds__(256)
void gat_wh_kernel(const float* __restrict__ h, const float* __restrict__ W,
                   const float* __restrict__ a, const float* __restrict__ mask) {
    __shared__ float h_s[32 * FIN];
    __shared__ float W_s[FIN * FO];

    int tid = threadIdx.x;
    size_t base = (size_t)blockIdx.x * 32;
    {
        const float4* hsrc = (const float4*)(h + base * FIN);
        float4* hdst = (float4*)h_s;
        #pragma unroll
        for (int r = 0; r < 4; r++) hdst[r * 256 + tid] = hsrc[r * 256 + tid];
        const float4* wsrc = (const float4*)W;
        float4* wdst = (float4*)W_s;
        #pragma unroll
        for (int r = 0; r < 8; r++) wdst[r * 256 + tid] = wsrc[r * 256 + tid];
    }
    __syncthreads();

    int r = tid >> 4, og = tid & 15;
    unsigned long long acc0 = 0, acc1 = 0, acc2 = 0, acc3 = 0;
    const float* hrowA = h_s + r * FIN;
    const float* hrowB = h_s + (r + 16) * FIN;
    #pragma unroll 4
    for (int k = 0; k < FIN; k += 4) {
        float4 ha = *(const float4*)(hrowA + k);
        float4 hb = *(const float4*)(hrowB + k);
        #pragma unroll
        for (int t = 0; t < 4; t++) {
            float va = (t == 0) ? ha.x : (t == 1) ? ha.y : (t == 2) ? ha.z : ha.w;
            float vb = (t == 0) ? hb.x : (t == 1) ? hb.y : (t == 2) ? hb.z : hb.w;
            ulonglong2 w = *(const ulonglong2*)(W_s + (k + t) * FO + og * 4);
            unsigned long long va2 = pack2(va, va), vb2 = pack2(vb, vb);
            fma2(acc0, va2, w.x); fma2(acc1, va2, w.y);
            fma2(acc2, vb2, w.x); fma2(acc3, vb2, w.y);
        }
    }
    int o = og * 4;
    #pragma unroll
    for (int half = 0; half < 2; half++) {
        float2 p01 = unpack2(half ? acc2 : acc0);
        float2 p23 = unpack2(half ? acc3 : acc1);
        size_t row = base + r + half * 16;
        ((float4*)(g_Wh + row * FO))[og] = make_float4(p01.x, p01.y, p23.x, p23.y);
        float ps = p01.x * a[o]      + p01.y * a[o + 1]      + p23.x * a[o + 2]      + p23.y * a[o + 3];
        float pd = p01.x * a[FO + o] + p01.y * a[FO + o + 1] + p23.x * a[FO + o + 2] + p23.y * a[FO + o + 3];
        #pragma unroll
        for (int off = 8; off >= 1; off >>= 1) {
            ps += __shfl_down_sync(0xffffffffu, ps, off, 16);
            pd += __shfl_down_sync(0xffffffffu, pd, off, 16);
        }
        if (og == 0) {
            bool ok = mask[row] > 0.f;
            g_fi[row] = ok ? ps : -1e30f;
            g_fj[row] = ok ? pd : -1e30f;
        }
    }
}

// ============================================================
// Kernel 1b: WhT split to bf16 hi/lo, n-major: WhT[b][o][j]
// ============================================================
__global__ __launch_bounds__(256)
void gat_wht_kernel() {
    __shared__ float tile[64][68];
    int tid = threadIdx.x;
    int j0 = blockIdx.x * 64;
    int b  = blockIdx.y;
    const float4* src = (const float4*)(g_Wh + (size_t)b * NN * FO + (size_t)j0 * FO);
    #pragma unroll
    for (int k = 0; k < 4; k++) {
        int idx = k * 256 + tid;
        int r = idx >> 4, c4 = idx & 15;
        float4 v = src[idx];
        tile[r][c4 * 4 + 0] = v.x; tile[r][c4 * 4 + 1] = v.y;
        tile[r][c4 * 4 + 2] = v.z; tile[r][c4 * 4 + 3] = v.w;
    }
    __syncthreads();
    int o = tid >> 2, cc = tid & 3;
    unsigned oh[8], ol[8];
    #pragma unroll
    for (int u = 0; u < 8; u++) {
        int j = cc * 16 + u * 2;
        split2(tile[j][o], tile[j + 1][o], oh[u], ol[u]);
    }
    size_t ob = (size_t)b * FO * (NN / 2) + (size_t)o * (NN / 2) + j0 / 2 + cc * 8;
    *(uint4*)(g_WhT_hi + ob)     = make_uint4(oh[0], oh[1], oh[2], oh[3]);
    *(uint4*)(g_WhT_hi + ob + 4) = make_uint4(oh[4], oh[5], oh[6], oh[7]);
    *(uint4*)(g_WhT_lo + ob)     = make_uint4(ol[0], ol[1], ol[2], ol[3]);
    *(uint4*)(g_WhT_lo + ob + 4) = make_uint4(ol[4], ol[5], ol[6], ol[7]);
}

// ============================================================
// Kernel 2: attention via ldmatrix + mma.sync (bf16 split x3).
// 256 threads / 8 warps, 3 blocks/SM. Warp w owns rows 16w..16w+15.
// p-stage: thread (row = tid&127, jhalf = tid>>7) does 32 edges.
// adj: direct LDG issued before the cp.async wait (latency under it).
// ============================================================
__device__ __forceinline__ void load_wh_tile(unsigned sbase, int buf, const unsigned* hi_g,
                                             const unsigned* lo_g, const float* fj_g,
                                             int jt, int tid) {
    #pragma unroll
    for (int k = 0; k < 2; k++) {
        int idx = tid + k * 256;              // 0..511
        int o = idx >> 3, cc = idx & 7;
        unsigned co = (unsigned)(((cc ^ (o & 7))) * 16);
        cpasync16(sbase + SM_WHHI + buf * 8192 + o * 128 + co,
                  hi_g + (size_t)o * (NN / 2) + jt * 32 + cc * 4);
        cpasync16(sbase + SM_WHLO + buf * 8192 + o * 128 + co,
                  lo_g + (size_t)o * (NN / 2) + jt * 32 + cc * 4);
    }
    if (tid < 16)
        cpasync16(sbase + SM_FJ + buf * 256 + tid * 16, fj_g + jt * TJ + tid * 4);
}

__global__ __launch_bounds__(256, 3)
void gat_attn_hmma(const float* __restrict__ adj,
                   float* __restrict__ part, float* __restrict__ rsum) {
    extern __shared__ char smem[];
    unsigned sbase = (unsigned)__cvta_generic_to_shared(smem);
    const int tid = threadIdx.x;
    const int wid = tid >> 5, lane = tid & 31;
    const int b = blockIdx.y, s = blockIdx.z;
    const int i0 = blockIdx.x * TI;
    const int jbeg = s * (NN / SPLITS);

    const int prow = tid & 127;       // p-stage i-row
    const int jh   = tid >> 7;        // 0/1: j-half of the tile

    const float* adj_r = adj + (size_t)b * NN * NN + (size_t)(i0 + prow) * NN + jbeg + jh * 32;
    const float* fj_g  = g_fj + b * NN + jbeg;
    const float  fiv   = g_fi[b * NN + i0 + prow];
    const unsigned* whhi_g = g_WhT_hi + (size_t)b * FO * (NN / 2) + jbeg / 2;
    const unsigned* whlo_g = g_WhT_lo + (size_t)b * FO * (NN / 2) + jbeg / 2;

    float dacc[8][4];
    #pragma unroll
    for (int nb = 0; nb < 8; nb++)
        #pragma unroll
        for (int z = 0; z < 4; z++) dacc[nb][z] = 0.f;
    float rowsum = 0.f;

    // prologue: wh(0) + fj(0)
    load_wh_tile(sbase, 0, whhi_g, whlo_g, fj_g, 0, tid);
    cpasync_commit();

    const int a_roff = ((lane >> 3) & 1) * 8 + (lane & 7);
    const int a_cs   = lane >> 4;
    const int b_roff = ((lane >> 4) << 3) + (lane & 7);
    const int b_cs   = (lane >> 3) & 1;
    const int asw    = prow & 7;

    for (int t = 0; t < NT; t++) {
        int c = t & 1;

        // issue adj LDGs for tile t FIRST (source order => before the wait asm)
        float4 av[8];
        {
            const float4* ap = (const float4*)(adj_r + t * TJ);
            #pragma unroll
            for (int k = 0; k < 8; k++) av[k] = ap[k];
        }

        cpasync_wait_all();
        __syncthreads();   // wh(t)/fj(t) visible; p(t-1) fully consumed

        // ---- p-stage: 32 edges/thread, rowsum partial, bf16 hi/lo ----
        {
            const float4* fp = (const float4*)(smem + SM_FJ + c * 256 + jh * 128);
            #pragma unroll
            for (int g = 0; g < 4; g++) {
                float4 a0 = av[2 * g], a1 = av[2 * g + 1];
                float4 f0 = fp[2 * g], f1 = fp[2 * g + 1];
                float p[8];
                {
                    float xs[8] = { fiv + f0.x, fiv + f0.y, fiv + f0.z, fiv + f0.w,
                                    fiv + f1.x, fiv + f1.y, fiv + f1.z, fiv + f1.w };
                    float aa[8] = { a0.x, a0.y, a0.z, a0.w, a1.x, a1.y, a1.z, a1.w };
                    #pragma unroll
                    for (int e = 0; e < 8; e++) {
                        float l = fmaxf(xs[e], ALPHA * xs[e]);
                        p[e] = (aa[e] > 0.f) ? __expf(l) : 0.f;
                        rowsum += p[e];
                    }
                }
                unsigned h0, h1, h2, h3, l0, l1, l2, l3;
                split2(p[0], p[1], h0, l0);
                split2(p[2], p[3], h1, l1);
                split2(p[4], p[5], h2, l2);
                split2(p[6], p[7], h3, l3);
                int chunk = jh * 4 + g;
                int co = (chunk ^ asw) << 4;
                *(uint4*)(smem + SM_PHI + prow * 128 + co) = make_uint4(h0, h1, h2, h3);
                *(uint4*)(smem + SM_PLO + prow * 128 + co) = make_uint4(l0, l1, l2, l3);
            }
        }
        __syncthreads();   // p(t) visible

        // prefetch wh(t+1): overlaps mma(t)
        if (t + 1 < NT) {
            load_wh_tile(sbase, 1 - c, whhi_g, whlo_g, fj_g, t + 1, tid);
            cpasync_commit();
        }

        // ---- mma stage: warp owns M=16 rows ----
        unsigned whb_hi = sbase + SM_WHHI + c * 8192;
        unsigned whb_lo = sbase + SM_WHLO + c * 8192;
        #pragma unroll
        for (int kb = 0; kb < 4; kb++) {
            unsigned ah[4], al[4];
            {
                int r = 16 * wid + a_roff;
                int cs = 2 * kb + a_cs;
                unsigned off = (unsigned)(r * 128 + ((cs ^ (r & 7)) << 4));
                ldm_x4(ah, sbase + SM_PHI + off);
                ldm_x4(al, sbase + SM_PLO + off);
            }
            #pragma unroll
            for (int nb2 = 0; nb2 < 4; nb2++) {
                unsigned bh[4], bl[4];
                int rn = nb2 * 16 + b_roff;
                int cs = 2 * kb + b_cs;
                unsigned off = (unsigned)(rn * 128 + ((cs ^ (rn & 7)) << 4));
                ldm_x4(bh, whb_hi + off);
                ldm_x4(bl, whb_lo + off);
                mma_bf16(dacc[2 * nb2],     ah, bh[0], bh[1]);
                mma_bf16(dacc[2 * nb2],     ah, bl[0], bl[1]);
                mma_bf16(dacc[2 * nb2],     al, bh[0], bh[1]);
                mma_bf16(dacc[2 * nb2 + 1], ah, bh[2], bh[3]);
                mma_bf16(dacc[2 * nb2 + 1], ah, bl[2], bl[3]);
                mma_bf16(dacc[2 * nb2 + 1], al, bh[2], bh[3]);
            }
        }
    }

    // ---- epilogue ----
    size_t rowbase = (size_t)s * BB * NN + (size_t)b * NN + i0;
    int r0 = 16 * wid + (lane >> 2);
    #pragma unroll
    for (int nb = 0; nb < 8; nb++) {
        int col = 8 * nb + 2 * (lane & 3);
        *(float2*)(part + (rowbase + r0) * FO + col)     = make_float2(dacc[nb][0], dacc[nb][1]);
        *(float2*)(part + (rowbase + r0 + 8) * FO + col) = make_float2(dacc[nb][2], dacc[nb][3]);
    }
    rsum[(size_t)(s * 2 + jh) * BB * NN + (size_t)b * NN + i0 + prow] = rowsum;
}

// ============================================================
// Kernel 3: reduce splits, normalize, relu
// ============================================================
__global__ __launch_bounds__(256)
void gat_reduce_kernel(const float* __restrict__ part,
                       const float* __restrict__ rsum,
                       float* __restrict__ out) {
    int t = blockIdx.x * blockDim.x + threadIdx.x;
    int rowi = t >> 4;
    float rs = 0.f;
    #pragma unroll
    for (int s = 0; s < SPLITS * 2; s++) rs += rsum[(size_t)s * BB * NN + rowi];
    float inv = (rs > 0.f) ? (1.f / rs) : 0.f;
    float4 v = make_float4(0.f, 0.f, 0.f, 0.f);
    #pragma unroll
    for (int s = 0; s < SPLITS; s++) {
        float4 pv = ((const float4*)part)[(size_t)s * BB * NN * 16 + t];
        v.x += pv.x; v.y += pv.y; v.z += pv.z; v.w += pv.w;
    }
    float4 o;
    o.x = fmaxf(v.x * inv, 0.f);
    o.y = fmaxf(v.y * inv, 0.f);
    o.z = fmaxf(v.z * inv, 0.f);
    o.w = fmaxf(v.w * inv, 0.f);
    ((float4*)out)[t] = o;
}

// ============================================================
extern "C" void kernel_launch(void* const* d_in, const int* in_sizes, int n_in,
                              void* d_out, int out_size) {
    const float *h = nullptr, *adj = nullptr, *mask = nullptr, *W = nullptr, *a = nullptr;
    for (int i = 0; i < n_in; i++) {
        switch (in_sizes[i]) {
            case BB * NN * FIN:  h    = (const float*)d_in[i]; break;
            case BB * NN * NN:   adj  = (const float*)d_in[i]; break;
            case BB * NN:        mask = (const float*)d_in[i]; break;
            case FIN * FO:       W    = (const float*)d_in[i]; break;
            case 2 * FO:         a    = (const float*)d_in[i]; break;
        }
    }
    float* out = (float*)d_out;
    float* part; cudaGetSymbolAddress((void**)&part, g_part);
    float* rsum; cudaGetSymbolAddress((void**)&rsum, g_rsum);

    static bool attr_set = false;
    if (!attr_set) {
        cudaFuncSetAttribute(gat_attn_hmma, cudaFuncAttributeMaxDynamicSharedMemorySize, SM_TOTAL);
        attr_set = true;
    }

    gat_wh_kernel<<<BB * NN / 32, 256>>>(h, W, a, mask);
    gat_wht_kernel<<<dim3(NN / 64, BB), 256>>>();
    gat_attn_hmma<<<dim3(NN / TI, BB, SPLITS), 256, SM_TOTAL>>>(adj, part, rsum);
    gat_reduce_kernel<<<BB * NN * 16 / 256, 256>>>(part, rsum, out);
}